// round 13
// baseline (speedup 1.0000x reference)
#include <cuda_runtime.h>
#include <math.h>
#include <float.h>

// ---------------- problem constants ----------------
#define NIMG 4
#define H 128
#define W 128
#define P 11
#define KSEL 16
#define WIN 65
#define V 32
#define S 3
#define HREF 40
#define WREF 40
#define LGRP (HREF*WREF)
#define WP 118              // H - P + 1
#define NPIX (H*W)
#define NPATCH (P*P)
#define NOFF 65
#define GB 2                // gh per band
#define NBAND 20            // bands (GB*NBAND = HREF)
#define BROWS 14            // 3*(GB-1) + P
#define NSLC 8              // oy slices per band
#define CHUNK 33            // ox chunk width
#define YSW 130             // padded Ys row stride
#define E_REG 30.25f
#define DE_REG 151.25f

// ---------------- device scratch ----------------
__device__ float g_pv[NIMG * HREF * NSLC * WREF * KSEL];
__device__ int   g_pi[NIMG * HREF * NSLC * WREF * KSEL];
__device__ int   g_ind[NIMG * LGRP * KSEL];
__device__ float2 g_acc[NIMG * NPIX];     // (num, den) fused

// ---------------- zero accumulators ----------------
__global__ void zero_kernel() {
    int i = blockIdx.x * blockDim.x + threadIdx.x;
    if (i < NIMG * NPIX) g_acc[i] = make_float2(0.f, 0.f);
}

// ---------------- fused block matching, 2-gh band + norm trick ------------
// CTA = (n, band of 2 gh, oy-slice); 256 threads.
// dist = ||a||^2 + ||b||^2 - 2 a.b : ref norms in regs, shifted norms NB[2][128]
// per oy, phase1 = pure 14-FMA dot product; phase2 = horizontal 11-sums +
// register top-16. Next-oy SH staging overlapped with last chunk's phase2.
__global__ __launch_bounds__(256) void bm_kernel(const float* __restrict__ y) {
    __shared__ float CS[GB][CHUNK][W];   // 33.8KB
    __shared__ float SH[BROWS][W];       // 7.2KB shifted strip
    __shared__ float NB[2][W];           // 1KB shifted-window norms

    const int blk  = blockIdx.x;
    const int s    = blk % NSLC;
    const int rest = blk / NSLC;
    const int bnd  = rest % NBAND;
    const int n    = rest / NBAND;
    const int gh0  = bnd * GB;
    const int t    = threadIdx.x;
    const int c    = t & 127;
    const int half = t >> 7;
    const float* img = y + n * NPIX;

    // reference band rows + norms in registers
    float a[BROWS];
#pragma unroll
    for (int r = 0; r < BROWS; r++) a[r] = __ldg(&img[(3 * gh0 + r) * W + c]);
    float na0 = 0.f, na1 = 0.f;
#pragma unroll
    for (int r = 0; r < BROWS; r++) {
        float v2 = a[r] * a[r];
        if (r <= P - 1) na0 += v2;
        if (r >= S)     na1 += v2;
    }

    // union oy range for the band, sliced
    const int lo  = max(-V, -3 * (gh0 + GB - 1));
    const int hi  = min(V, (H - P) - 3 * gh0);
    const int cnt = hi - lo + 1;
    const int s0  = lo + (cnt * s) / NSLC;
    const int s1  = lo + (cnt * (s + 1)) / NSLC;

    // phase-2 role: t < 240 -> (gwid, ghl, q)
    const int gwid = t % WREF;
    const int ghl  = (t / WREF) & 1;
    const int q    = t / (2 * WREF);       // 0..2
    float vals[KSEL];
    unsigned ip[KSEL / 2];
#pragma unroll
    for (int j = 0; j < KSEL; j++) vals[j] = FLT_MAX;
#pragma unroll
    for (int j = 0; j < KSEL / 2; j++) ip[j] = 0;
    float cmax = FLT_MAX; int am = 0;

    // initial SH stage for oy = s0
    for (int i = t; i < BROWS * W; i += 256) {
        int r = i >> 7, cc = i & 127;
        int rs = min(max(3 * gh0 + r + s0, 0), H - 1);
        SH[r][cc] = __ldg(&img[rs * W + cc]);
    }
    __syncthreads();

    for (int oy = s0; oy < s1; oy++) {
        // per-oy shifted norms (half 0 -> NB0, half 1 -> NB1)
        {
            float nb = 0.f;
            if (half == 0) {
#pragma unroll
                for (int r = 0; r <= P - 1; r++) { float v = SH[r][c]; nb += v * v; }
                NB[0][c] = nb;
            } else {
#pragma unroll
                for (int r = S; r < BROWS; r++) { float v = SH[r][c]; nb += v * v; }
                NB[1][c] = nb;
            }
        }
        __syncthreads();

#pragma unroll
        for (int ch = 0; ch < 2; ch++) {
            const int oxbase = ch * CHUNK;
            const int ccnt   = ch ? (NOFF - CHUNK) : CHUNK;   // 33 / 32

            // ---- phase 1: dot products + norm combine ----
            for (int oxl = half; oxl < ccnt; oxl += 2) {
                int cb = min(max(c + oxbase + oxl - V, 0), W - 1);
                float head = 0.f, mid = 0.f, tail = 0.f;
#pragma unroll
                for (int r = 0; r < S; r++)       head = fmaf(a[r], SH[r][cb], head);
#pragma unroll
                for (int r = S; r <= P - 1; r++)  mid  = fmaf(a[r], SH[r][cb], mid);
#pragma unroll
                for (int r = P; r < BROWS; r++)   tail = fmaf(a[r], SH[r][cb], tail);
                CS[0][oxl][c] = fmaf(-2.f, head + mid, na0 + NB[0][cb]);
                CS[1][oxl][c] = fmaf(-2.f, mid + tail, na1 + NB[1][cb]);
            }
            __syncthreads();

            // ---- phase 2: horizontal 11-sums + top-16 ----
            if (t < 2 * WREF * 3) {
                int gh = gh0 + ghl;
                if ((unsigned)(3 * gh + oy) <= (unsigned)(H - P)) {
                    for (int oxl = q; oxl < ccnt; oxl += 3) {
                        int oxi = oxbase + oxl;
                        int ox  = oxi - V;
                        int ccand = 3 * gwid + ox;
                        if ((unsigned)ccand > (unsigned)(W - P)) continue;
                        const float* row = &CS[ghl][oxl][3 * gwid];
                        float d = 0.f;
#pragma unroll
                        for (int b = 0; b < P; b++) d += row[b];
                        if (oy == 0 && ox == 0) d = -FLT_MAX;
                        if (d < cmax) {
                            vals[am] = d;
                            unsigned o = (unsigned)((oy + V) * NOFF + oxi);
                            if (am & 1) ip[am >> 1] = (ip[am >> 1] & 0x0000FFFFu) | (o << 16);
                            else        ip[am >> 1] = (ip[am >> 1] & 0xFFFF0000u) | o;
                            cmax = vals[0]; am = 0;
#pragma unroll
                            for (int j = 1; j < KSEL; j++)
                                if (vals[j] > cmax) { cmax = vals[j]; am = j; }
                        }
                    }
                }
            }
            // ---- overlapped: stage next oy's SH during last chunk's phase2 ----
            if (ch == 1 && oy + 1 < s1) {
                for (int i = t; i < BROWS * W; i += 256) {
                    int r = i >> 7, cc = i & 127;
                    int rs = min(max(3 * gh0 + r + oy + 1, 0), H - 1);
                    SH[r][cc] = __ldg(&img[rs * W + cc]);
                }
            }
            __syncthreads();
        }
    }

    // ---- in-CTA merge over q: 3x16 -> 16 per (ghl,gwid); overlay CS ----
    float* MV = &CS[0][0][0];                 // [80 groups][3][16]
    int*   MI = (int*)MV + 80 * 3 * KSEL;
    if (t < 240) {
        int grp = ghl * WREF + gwid;
#pragma unroll
        for (int j = 0; j < KSEL; j++) {
            unsigned o = (j & 1) ? (ip[j >> 1] >> 16) : (ip[j >> 1] & 0xFFFFu);
            MV[(grp * 3 + q) * KSEL + j] = vals[j];
            MI[(grp * 3 + q) * KSEL + j] = (int)o;
        }
    }
    __syncthreads();
    if (t < 80) {
        float* mv = &MV[t * 3 * KSEL];
        int*   mi = &MI[t * 3 * KSEL];
        int gh = gh0 + (t / WREF);
        int gw = t % WREF;
        size_t base = ((((size_t)n * HREF + gh) * NSLC + s) * WREF + gw) * KSEL;
        for (int sel = 0; sel < KSEL; sel++) {
            float bv = FLT_MAX; int bs = 0;
#pragma unroll
            for (int m = 0; m < 3 * KSEL; m++) {
                float v = mv[m];
                if (v < bv) { bv = v; bs = m; }
            }
            g_pv[base + sel] = bv;
            g_pi[base + sel] = mi[bs];
            mv[bs] = FLT_MAX;
        }
    }
}

// ---------------- cross-slice merge: 8x16 -> final 16 ----------------
__global__ __launch_bounds__(64) void bm_merge_kernel() {
    const int gh = blockIdx.x % HREF;
    const int n  = blockIdx.x / HREF;
    const int gw = threadIdx.x;
    if (gw >= WREF) return;

    const size_t gbase = ((size_t)n * HREF + gh) * NSLC;

    float vals[KSEL];
    int   idxs[KSEL];
#pragma unroll
    for (int j = 0; j < KSEL; j++) { vals[j] = FLT_MAX; idxs[j] = 0; }
    float cmax = FLT_MAX; int am = 0;

    for (int sl = 0; sl < NSLC; sl++) {
        const float* pv = &g_pv[((gbase + sl) * WREF + gw) * KSEL];
        const int*   pi = &g_pi[((gbase + sl) * WREF + gw) * KSEL];
#pragma unroll
        for (int m = 0; m < KSEL; m++) {
            float v = pv[m];
            if (v < cmax) {
                vals[am] = v; idxs[am] = pi[m];
                cmax = vals[0]; am = 0;
#pragma unroll
                for (int j = 1; j < KSEL; j++)
                    if (vals[j] > cmax) { cmax = vals[j]; am = j; }
            }
        }
    }

    int* out = &g_ind[((n * LGRP) + gh * WREF + gw) * KSEL];
#pragma unroll
    for (int j = 0; j < KSEL; j++) {
        int o = idxs[j];
        int oy = o / NOFF - V, ox = o % NOFF - V;
        out[j] = (3 * gh + oy) * WP + (3 * gw + ox);
    }
}

// ---------------- gather + denoise + scatter (float2 atomics) -------------
__global__ __launch_bounds__(128) void denoise_kernel(const float* __restrict__ y) {
    __shared__ float Ys[KSEL][YSW];          // stride 130 (bank-spread rows)
    __shared__ float Qp[2][64][5];           // Q e-half partials (padded)
    __shared__ float Qs[KSEL][KSEL + 1];
    __shared__ float Qi[KSEL][KSEL + 1];
    __shared__ float Th[KSEL][KSEL + 1];
    __shared__ float wgt[KSEL];
    __shared__ float q1[KSEL];
    __shared__ float q2s;
    __shared__ int   pr[KSEL], pc[KSEL];

    const int g = blockIdx.x;
    const int n = g / LGRP;
    const int tid = threadIdx.x;
    const float* img = y + n * NPIX;

    if (tid < KSEL) {
        int idx = g_ind[g * KSEL + tid];
        pr[tid] = idx / WP;
        pc[tid] = idx % WP;
    }
    __syncthreads();

    for (int t = tid; t < KSEL * NPATCH; t += 128) {
        int i = t / NPATCH, e = t % NPATCH;
        int a = e / P, b = e % P;
        Ys[i][e] = img[(pr[i] + a) * W + pc[i] + b];
    }
    __syncthreads();

    // Q = Y Y^T + E I : 2x2 register tiling, e split in halves
    {
        int quad = tid & 63;
        int eh   = tid >> 6;
        int i0 = (quad >> 3) << 1, j0 = (quad & 7) << 1;
        float q00 = 0.f, q01 = 0.f, q10 = 0.f, q11 = 0.f;
        int e0 = eh ? 61 : 0, e1 = eh ? NPATCH : 61;
        for (int e = e0; e < e1; e++) {
            float yi0 = Ys[i0][e], yi1 = Ys[i0 + 1][e];
            float yj0 = Ys[j0][e], yj1 = Ys[j0 + 1][e];
            q00 = fmaf(yi0, yj0, q00);
            q01 = fmaf(yi0, yj1, q01);
            q10 = fmaf(yi1, yj0, q10);
            q11 = fmaf(yi1, yj1, q11);
        }
        Qp[eh][quad][0] = q00; Qp[eh][quad][1] = q01;
        Qp[eh][quad][2] = q10; Qp[eh][quad][3] = q11;
    }
    __syncthreads();
    if (tid < 64) {
        int i0 = (tid >> 3) << 1, j0 = (tid & 7) << 1;
        float q00 = Qp[0][tid][0] + Qp[1][tid][0];
        float q01 = Qp[0][tid][1] + Qp[1][tid][1];
        float q10 = Qp[0][tid][2] + Qp[1][tid][2];
        float q11 = Qp[0][tid][3] + Qp[1][tid][3];
        if (i0 == j0) { q00 += E_REG; q11 += E_REG; }
        Qs[i0][j0] = q00;     Qs[i0][j0 + 1] = q01;
        Qs[i0 + 1][j0] = q10; Qs[i0 + 1][j0 + 1] = q11;
    }
    __syncthreads();

    if (tid < 32) {
        int lane = tid;
        for (int j = 0; j < KSEL; j++) {
            if (lane == 0) Qs[j][j] = sqrtf(Qs[j][j]);
            __syncwarp();
            float dj = Qs[j][j];
            if (lane > j && lane < KSEL) Qs[lane][j] /= dj;
            __syncwarp();
            if (lane > j && lane < KSEL) {
                float lij = Qs[lane][j];
                for (int m = j + 1; m <= lane; m++) Qs[lane][m] -= lij * Qs[m][j];
            }
            __syncwarp();
        }
        if (lane < KSEL) {
            float z[KSEL];
            for (int i = 0; i < KSEL; i++) {
                float s = (i == lane) ? 1.f : 0.f;
                for (int j = 0; j < i; j++) s -= Qs[i][j] * z[j];
                z[i] = s / Qs[i][i];
            }
            for (int i = KSEL - 1; i >= 0; i--) {
                float s = z[i];
                for (int j = i + 1; j < KSEL; j++) s -= Qs[j][i] * z[j];
                z[i] = s / Qs[i][i];
            }
            for (int i = 0; i < KSEL; i++) Qi[i][lane] = z[i];
        }
    }
    __syncthreads();

    if (tid < KSEL) {
        float s = 0.f;
        for (int j = 0; j < KSEL; j++) s += Qi[tid][j];
        q1[tid] = s;
    }
    __syncthreads();
    if (tid == 0) {
        float s = 0.f;
        for (int i = 0; i < KSEL; i++) s += q1[i];
        q2s = s;
    }
    __syncthreads();
    for (int t = tid; t < KSEL * KSEL; t += 128) {
        int i = t / KSEL, j = t % KSEL;
        Th[i][j] = ((i == j) ? 1.f : 0.f) - (Qi[i][j] - q1[i] * q1[j] / q2s) * DE_REG;
    }
    __syncthreads();
    if (tid < KSEL) {
        float s = 0.f;
        for (int j = 0; j < KSEL; j++) s += Th[tid][j] * Th[tid][j];
        s = fminf(fmaxf(s, 1.f / (float)KSEL), 1.f);
        wgt[tid] = 1.f / s;
    }
    __syncthreads();

    // X_hat = theta @ Y with theta row in registers; fused float2 scatter
    float2* accI = g_acc + n * NPIX;
    {
        int i  = tid >> 3;       // patch
        int l8 = tid & 7;        // pixel stripe
        float tr[KSEL];
#pragma unroll
        for (int j = 0; j < KSEL; j++) tr[j] = Th[i][j];
        float wv = wgt[i];
        int prI = pr[i], pcI = pc[i];
        for (int e = l8; e < NPATCH; e += 8) {
            float s = 0.f;
#pragma unroll
            for (int j = 0; j < KSEL; j++) s = fmaf(tr[j], Ys[j][e], s);
            int aRow = e / P, b = e % P;
            int pix = (prI + aRow) * W + pcI + b;
            atomicAdd(&accI[pix], make_float2(s * wv, wv));
        }
    }
}

// ---------------- final divide ----------------
__global__ void div_kernel(float* __restrict__ out) {
    int i = blockIdx.x * blockDim.x + threadIdx.x;
    if (i < NIMG * NPIX) {
        float2 v = g_acc[i];
        out[i] = v.x / v.y;
    }
}

extern "C" void kernel_launch(void* const* d_in, const int* in_sizes, int n_in,
                              void* d_out, int out_size) {
    const float* y = (const float*)d_in[0];
    float* out = (float*)d_out;

    zero_kernel<<<(NIMG * NPIX + 255) / 256, 256>>>();

    bm_kernel<<<NIMG * NBAND * NSLC, 256>>>(y);

    bm_merge_kernel<<<NIMG * HREF, 64>>>();

    denoise_kernel<<<NIMG * LGRP, 128>>>(y);

    div_kernel<<<(NIMG * NPIX + 255) / 256, 256>>>(out);
}

// round 14
// speedup vs baseline: 1.0694x; 1.0694x over previous
#include <cuda_runtime.h>
#include <math.h>
#include <float.h>

// ---------------- problem constants ----------------
#define NIMG 4
#define H 128
#define W 128
#define P 11
#define KSEL 16
#define WIN 65
#define V 32
#define S 3
#define HREF 40
#define WREF 40
#define LGRP (HREF*WREF)
#define WP 118              // H - P + 1
#define NPIX (H*W)
#define NPATCH (P*P)
#define NOFF 65
#define GB 2                // gh per band
#define NBAND 20            // bands (GB*NBAND = HREF)
#define BROWS 14            // 3*(GB-1) + P
#define NSLC 8              // oy slices per band
#define CHUNK 33            // ox chunk width
#define YSW 130             // padded Ys row stride
#define E_REG 30.25f
#define DE_REG 151.25f

// ---------------- device scratch ----------------
__device__ float g_pv[NIMG * HREF * NSLC * WREF * KSEL];
__device__ int   g_pi[NIMG * HREF * NSLC * WREF * KSEL];
__device__ int   g_ind[NIMG * LGRP * KSEL];
__device__ float2 g_acc[NIMG * NPIX];     // (num, den) fused

// ---------------- zero accumulators ----------------
__global__ void zero_kernel() {
    int i = blockIdx.x * blockDim.x + threadIdx.x;
    if (i < NIMG * NPIX) g_acc[i] = make_float2(0.f, 0.f);
}

// ---------------- fused block matching, 2-gh band version (R12) -----------
// CTA = (n, band of 2 gh, oy-slice); 256 threads.
// Per oy, per 33-wide ox chunk: phase1 computes BOTH gh column sums from one
// d^2 per row; phase2: 240 threads = 80 groups x 3 ox stripes. Next-oy SH
// staging is overlapped with phase2 of the last chunk (4 barriers/oy).
__global__ __launch_bounds__(256) void bm_kernel(const float* __restrict__ y) {
    __shared__ float CS[GB][CHUNK][W];   // 33.8KB
    __shared__ float SH[BROWS][W];       // 7.2KB shifted strip

    const int blk  = blockIdx.x;
    const int s    = blk % NSLC;
    const int rest = blk / NSLC;
    const int bnd  = rest % NBAND;
    const int n    = rest / NBAND;
    const int gh0  = bnd * GB;
    const int t    = threadIdx.x;
    const int c    = t & 127;
    const int half = t >> 7;
    const float* img = y + n * NPIX;

    // reference band rows in registers (rows 3*gh0 .. 3*gh0+13, in-bounds)
    float a[BROWS];
#pragma unroll
    for (int r = 0; r < BROWS; r++) a[r] = __ldg(&img[(3 * gh0 + r) * W + c]);

    // union oy range for the band, sliced
    const int lo  = max(-V, -3 * (gh0 + GB - 1));
    const int hi  = min(V, (H - P) - 3 * gh0);
    const int cnt = hi - lo + 1;
    const int s0  = lo + (cnt * s) / NSLC;
    const int s1  = lo + (cnt * (s + 1)) / NSLC;

    // phase-2 role: t < 240 -> (gwid, ghl, q)
    const int gwid = t % WREF;
    const int ghl  = (t / WREF) & 1;
    const int q    = t / (2 * WREF);       // 0..2
    float vals[KSEL];
    unsigned ip[KSEL / 2];
#pragma unroll
    for (int j = 0; j < KSEL; j++) vals[j] = FLT_MAX;
#pragma unroll
    for (int j = 0; j < KSEL / 2; j++) ip[j] = 0;
    float cmax = FLT_MAX; int am = 0;

    // initial SH stage for oy = s0
    for (int i = t; i < BROWS * W; i += 256) {
        int r = i >> 7, cc = i & 127;
        int rs = min(max(3 * gh0 + r + s0, 0), H - 1);
        SH[r][cc] = __ldg(&img[rs * W + cc]);
    }
    __syncthreads();

    for (int oy = s0; oy < s1; oy++) {
#pragma unroll
        for (int ch = 0; ch < 2; ch++) {
            const int oxbase = ch * CHUNK;
            const int ccnt   = ch ? (NOFF - CHUNK) : CHUNK;   // 33 / 32

            // ---- phase 1: both gh column sums in one pass ----
            for (int oxl = half; oxl < ccnt; oxl += 2) {
                int cb = min(max(c + oxbase + oxl - V, 0), W - 1);
                float cs0 = 0.f, cs1 = 0.f;
#pragma unroll
                for (int r = 0; r < BROWS; r++) {
                    float d = a[r] - SH[r][cb];
                    float d2 = d * d;
                    if (r <= P - 1) cs0 += d2;     // gh0: rows 0..10
                    if (r >= S)     cs1 += d2;     // gh0+1: rows 3..13
                }
                CS[0][oxl][c] = cs0;
                CS[1][oxl][c] = cs1;
            }
            __syncthreads();

            // ---- phase 2: horizontal 11-sums + top-16 ----
            if (t < 2 * WREF * 3) {
                int gh = gh0 + ghl;
                if ((unsigned)(3 * gh + oy) <= (unsigned)(H - P)) {
                    for (int oxl = q; oxl < ccnt; oxl += 3) {
                        int oxi = oxbase + oxl;
                        int ox  = oxi - V;
                        int ccand = 3 * gwid + ox;
                        if ((unsigned)ccand > (unsigned)(W - P)) continue;
                        const float* row = &CS[ghl][oxl][3 * gwid];
                        float d = 0.f;
#pragma unroll
                        for (int b = 0; b < P; b++) d += row[b];
                        if (oy == 0 && ox == 0) d = -FLT_MAX;
                        if (d < cmax) {
                            vals[am] = d;
                            unsigned o = (unsigned)((oy + V) * NOFF + oxi);
                            if (am & 1) ip[am >> 1] = (ip[am >> 1] & 0x0000FFFFu) | (o << 16);
                            else        ip[am >> 1] = (ip[am >> 1] & 0xFFFF0000u) | o;
                            cmax = vals[0]; am = 0;
#pragma unroll
                            for (int j = 1; j < KSEL; j++)
                                if (vals[j] > cmax) { cmax = vals[j]; am = j; }
                        }
                    }
                }
            }
            // ---- overlapped: stage next oy's SH during last chunk's phase2 ----
            if (ch == 1 && oy + 1 < s1) {
                for (int i = t; i < BROWS * W; i += 256) {
                    int r = i >> 7, cc = i & 127;
                    int rs = min(max(3 * gh0 + r + oy + 1, 0), H - 1);
                    SH[r][cc] = __ldg(&img[rs * W + cc]);
                }
            }
            __syncthreads();
        }
    }

    // ---- in-CTA merge over q: 3x16 -> 16 per (ghl,gwid); overlay CS ----
    float* MV = &CS[0][0][0];                 // [80 groups][3][16]
    int*   MI = (int*)MV + 80 * 3 * KSEL;
    if (t < 240) {
        int grp = ghl * WREF + gwid;
#pragma unroll
        for (int j = 0; j < KSEL; j++) {
            unsigned o = (j & 1) ? (ip[j >> 1] >> 16) : (ip[j >> 1] & 0xFFFFu);
            MV[(grp * 3 + q) * KSEL + j] = vals[j];
            MI[(grp * 3 + q) * KSEL + j] = (int)o;
        }
    }
    __syncthreads();
    if (t < 80) {
        float* mv = &MV[t * 3 * KSEL];
        int*   mi = &MI[t * 3 * KSEL];
        int gh = gh0 + (t / WREF);
        int gw = t % WREF;
        size_t base = ((((size_t)n * HREF + gh) * NSLC + s) * WREF + gw) * KSEL;
        for (int sel = 0; sel < KSEL; sel++) {
            float bv = FLT_MAX; int bs = 0;
#pragma unroll
            for (int m = 0; m < 3 * KSEL; m++) {
                float v = mv[m];
                if (v < bv) { bv = v; bs = m; }
            }
            g_pv[base + sel] = bv;
            g_pi[base + sel] = mi[bs];
            mv[bs] = FLT_MAX;
        }
    }
}

// ---------------- cross-slice merge: 8x16 -> final 16 ----------------
__global__ __launch_bounds__(64) void bm_merge_kernel() {
    const int gh = blockIdx.x % HREF;
    const int n  = blockIdx.x / HREF;
    const int gw = threadIdx.x;
    if (gw >= WREF) return;

    const size_t gbase = ((size_t)n * HREF + gh) * NSLC;

    float vals[KSEL];
    int   idxs[KSEL];
#pragma unroll
    for (int j = 0; j < KSEL; j++) { vals[j] = FLT_MAX; idxs[j] = 0; }
    float cmax = FLT_MAX; int am = 0;

    for (int sl = 0; sl < NSLC; sl++) {
        const float* pv = &g_pv[((gbase + sl) * WREF + gw) * KSEL];
        const int*   pi = &g_pi[((gbase + sl) * WREF + gw) * KSEL];
#pragma unroll
        for (int m = 0; m < KSEL; m++) {
            float v = pv[m];
            if (v < cmax) {
                vals[am] = v; idxs[am] = pi[m];
                cmax = vals[0]; am = 0;
#pragma unroll
                for (int j = 1; j < KSEL; j++)
                    if (vals[j] > cmax) { cmax = vals[j]; am = j; }
            }
        }
    }

    int* out = &g_ind[((n * LGRP) + gh * WREF + gw) * KSEL];
#pragma unroll
    for (int j = 0; j < KSEL; j++) {
        int o = idxs[j];
        int oy = o / NOFF - V, ox = o % NOFF - V;
        out[j] = (3 * gh + oy) * WP + (3 * gw + ox);
    }
}

// ---------------- gather + denoise + scatter (float2 atomics) -------------
__global__ __launch_bounds__(128) void denoise_kernel(const float* __restrict__ y) {
    __shared__ float Ys[KSEL][YSW];          // stride 130 (bank-spread rows)
    __shared__ float Qp[2][64][5];           // Q e-half partials (padded)
    __shared__ float Qs[KSEL][KSEL + 1];
    __shared__ float Qi[KSEL][KSEL + 1];
    __shared__ float Th[KSEL][KSEL + 1];
    __shared__ float wgt[KSEL];
    __shared__ float q1[KSEL];
    __shared__ float q2s;
    __shared__ int   pr[KSEL], pc[KSEL];

    const int g = blockIdx.x;
    const int n = g / LGRP;
    const int tid = threadIdx.x;
    const float* img = y + n * NPIX;

    if (tid < KSEL) {
        int idx = g_ind[g * KSEL + tid];
        pr[tid] = idx / WP;
        pc[tid] = idx % WP;
    }
    __syncthreads();

    for (int t = tid; t < KSEL * NPATCH; t += 128) {
        int i = t / NPATCH, e = t % NPATCH;
        int a = e / P, b = e % P;
        Ys[i][e] = img[(pr[i] + a) * W + pc[i] + b];
    }
    __syncthreads();

    // Q = Y Y^T + E I : 2x2 register tiling, e split in halves
    {
        int quad = tid & 63;
        int eh   = tid >> 6;
        int i0 = (quad >> 3) << 1, j0 = (quad & 7) << 1;
        float q00 = 0.f, q01 = 0.f, q10 = 0.f, q11 = 0.f;
        int e0 = eh ? 61 : 0, e1 = eh ? NPATCH : 61;
        for (int e = e0; e < e1; e++) {
            float yi0 = Ys[i0][e], yi1 = Ys[i0 + 1][e];
            float yj0 = Ys[j0][e], yj1 = Ys[j0 + 1][e];
            q00 = fmaf(yi0, yj0, q00);
            q01 = fmaf(yi0, yj1, q01);
            q10 = fmaf(yi1, yj0, q10);
            q11 = fmaf(yi1, yj1, q11);
        }
        Qp[eh][quad][0] = q00; Qp[eh][quad][1] = q01;
        Qp[eh][quad][2] = q10; Qp[eh][quad][3] = q11;
    }
    __syncthreads();
    if (tid < 64) {
        int i0 = (tid >> 3) << 1, j0 = (tid & 7) << 1;
        float q00 = Qp[0][tid][0] + Qp[1][tid][0];
        float q01 = Qp[0][tid][1] + Qp[1][tid][1];
        float q10 = Qp[0][tid][2] + Qp[1][tid][2];
        float q11 = Qp[0][tid][3] + Qp[1][tid][3];
        if (i0 == j0) { q00 += E_REG; q11 += E_REG; }
        Qs[i0][j0] = q00;     Qs[i0][j0 + 1] = q01;
        Qs[i0 + 1][j0] = q10; Qs[i0 + 1][j0 + 1] = q11;
    }
    __syncthreads();

    if (tid < 32) {
        int lane = tid;
        for (int j = 0; j < KSEL; j++) {
            if (lane == 0) Qs[j][j] = sqrtf(Qs[j][j]);
            __syncwarp();
            float dj = Qs[j][j];
            if (lane > j && lane < KSEL) Qs[lane][j] /= dj;
            __syncwarp();
            if (lane > j && lane < KSEL) {
                float lij = Qs[lane][j];
                for (int m = j + 1; m <= lane; m++) Qs[lane][m] -= lij * Qs[m][j];
            }
            __syncwarp();
        }
        if (lane < KSEL) {
            float z[KSEL];
            for (int i = 0; i < KSEL; i++) {
                float s = (i == lane) ? 1.f : 0.f;
                for (int j = 0; j < i; j++) s -= Qs[i][j] * z[j];
                z[i] = s / Qs[i][i];
            }
            for (int i = KSEL - 1; i >= 0; i--) {
                float s = z[i];
                for (int j = i + 1; j < KSEL; j++) s -= Qs[j][i] * z[j];
                z[i] = s / Qs[i][i];
            }
            for (int i = 0; i < KSEL; i++) Qi[i][lane] = z[i];
        }
    }
    __syncthreads();

    if (tid < KSEL) {
        float s = 0.f;
        for (int j = 0; j < KSEL; j++) s += Qi[tid][j];
        q1[tid] = s;
    }
    __syncthreads();
    if (tid == 0) {
        float s = 0.f;
        for (int i = 0; i < KSEL; i++) s += q1[i];
        q2s = s;
    }
    __syncthreads();
    for (int t = tid; t < KSEL * KSEL; t += 128) {
        int i = t / KSEL, j = t % KSEL;
        Th[i][j] = ((i == j) ? 1.f : 0.f) - (Qi[i][j] - q1[i] * q1[j] / q2s) * DE_REG;
    }
    __syncthreads();
    if (tid < KSEL) {
        float s = 0.f;
        for (int j = 0; j < KSEL; j++) s += Th[tid][j] * Th[tid][j];
        s = fminf(fmaxf(s, 1.f / (float)KSEL), 1.f);
        wgt[tid] = 1.f / s;
    }
    __syncthreads();

    // X_hat = theta @ Y with theta row in registers; fused float2 scatter
    float2* accI = g_acc + n * NPIX;
    {
        int i  = tid >> 3;       // patch
        int l8 = tid & 7;        // pixel stripe
        float tr[KSEL];
#pragma unroll
        for (int j = 0; j < KSEL; j++) tr[j] = Th[i][j];
        float wv = wgt[i];
        int prI = pr[i], pcI = pc[i];
        for (int e = l8; e < NPATCH; e += 8) {
            float s = 0.f;
#pragma unroll
            for (int j = 0; j < KSEL; j++) s = fmaf(tr[j], Ys[j][e], s);
            int aRow = e / P, b = e % P;
            int pix = (prI + aRow) * W + pcI + b;
            atomicAdd(&accI[pix], make_float2(s * wv, wv));
        }
    }
}

// ---------------- final divide ----------------
__global__ void div_kernel(float* __restrict__ out) {
    int i = blockIdx.x * blockDim.x + threadIdx.x;
    if (i < NIMG * NPIX) {
        float2 v = g_acc[i];
        out[i] = v.x / v.y;
    }
}

extern "C" void kernel_launch(void* const* d_in, const int* in_sizes, int n_in,
                              void* d_out, int out_size) {
    const float* y = (const float*)d_in[0];
    float* out = (float*)d_out;

    zero_kernel<<<(NIMG * NPIX + 255) / 256, 256>>>();

    bm_kernel<<<NIMG * NBAND * NSLC, 256>>>(y);

    bm_merge_kernel<<<NIMG * HREF, 64>>>();

    denoise_kernel<<<NIMG * LGRP, 128>>>(y);

    div_kernel<<<(NIMG * NPIX + 255) / 256, 256>>>(out);
}

// round 15
// speedup vs baseline: 1.1062x; 1.0344x over previous
#include <cuda_runtime.h>
#include <math.h>
#include <float.h>

// ---------------- problem constants ----------------
#define NIMG 4
#define H 128
#define W 128
#define P 11
#define KSEL 16
#define WIN 65
#define V 32
#define S 3
#define HREF 40
#define WREF 40
#define LGRP (HREF*WREF)
#define WP 118              // H - P + 1
#define NPIX (H*W)
#define NPATCH (P*P)
#define NOFF 65
#define GB 2                // gh per band
#define NBAND 20            // bands (GB*NBAND = HREF)
#define BROWS 14            // 3*(GB-1) + P
#define NSLC 8              // oy slices per band
#define CHUNK 33            // ox chunk width
#define YSW 130             // padded Ys row stride
#define E_REG 30.25f
#define DE_REG 151.25f

// ---------------- device scratch ----------------
__device__ float g_pv[NIMG * HREF * NSLC * WREF * KSEL];
__device__ int   g_pi[NIMG * HREF * NSLC * WREF * KSEL];
__device__ float2 g_acc[NIMG * NPIX];     // (num, den) fused

// ---------------- fused block matching, 2-gh band version -----------------
// CTA = (n, band of 2 gh, oy-slice); 256 threads.
// Per oy, per 33-wide ox chunk: phase1 computes BOTH gh column sums from one
// d^2 per row via head/mid/tail FFMA split; phase2: 240 threads = 80 groups
// x 3 ox stripes. Next-oy SH staging overlapped with phase2 of last chunk.
// Also zeroes g_acc (denoise accumulators) at entry.
__global__ __launch_bounds__(256) void bm_kernel(const float* __restrict__ y) {
    __shared__ float CS[GB][CHUNK][W];   // 33.8KB
    __shared__ float SH[BROWS][W];       // 7.2KB shifted strip

    const int blk  = blockIdx.x;
    const int t    = threadIdx.x;

    // fold in accumulator zeroing (640*256 threads cover 65536 elems)
    {
        int z = blk * 256 + t;
        if (z < NIMG * NPIX) g_acc[z] = make_float2(0.f, 0.f);
    }

    const int s    = blk % NSLC;
    const int rest = blk / NSLC;
    const int bnd  = rest % NBAND;
    const int n    = rest / NBAND;
    const int gh0  = bnd * GB;
    const int c    = t & 127;
    const int half = t >> 7;
    const float* img = y + n * NPIX;

    // reference band rows in registers (rows 3*gh0 .. 3*gh0+13, in-bounds)
    float a[BROWS];
#pragma unroll
    for (int r = 0; r < BROWS; r++) a[r] = __ldg(&img[(3 * gh0 + r) * W + c]);

    // union oy range for the band, sliced
    const int lo  = max(-V, -3 * (gh0 + GB - 1));
    const int hi  = min(V, (H - P) - 3 * gh0);
    const int cnt = hi - lo + 1;
    const int s0  = lo + (cnt * s) / NSLC;
    const int s1  = lo + (cnt * (s + 1)) / NSLC;

    // phase-2 role: t < 240 -> (gwid, ghl, q)
    const int gwid = t % WREF;
    const int ghl  = (t / WREF) & 1;
    const int q    = t / (2 * WREF);       // 0..2
    float vals[KSEL];
    unsigned ip[KSEL / 2];
#pragma unroll
    for (int j = 0; j < KSEL; j++) vals[j] = FLT_MAX;
#pragma unroll
    for (int j = 0; j < KSEL / 2; j++) ip[j] = 0;
    float cmax = FLT_MAX; int am = 0;

    // initial SH stage for oy = s0
    for (int i = t; i < BROWS * W; i += 256) {
        int r = i >> 7, cc = i & 127;
        int rs = min(max(3 * gh0 + r + s0, 0), H - 1);
        SH[r][cc] = __ldg(&img[rs * W + cc]);
    }
    __syncthreads();

    for (int oy = s0; oy < s1; oy++) {
#pragma unroll
        for (int ch = 0; ch < 2; ch++) {
            const int oxbase = ch * CHUNK;
            const int ccnt   = ch ? (NOFF - CHUNK) : CHUNK;   // 33 / 32

            // ---- phase 1: head/mid/tail FFMA split ----
            for (int oxl = half; oxl < ccnt; oxl += 2) {
                int cb = min(max(c + oxbase + oxl - V, 0), W - 1);
                float head = 0.f, mid = 0.f, tail = 0.f;
#pragma unroll
                for (int r = 0; r < S; r++) {
                    float d = a[r] - SH[r][cb];
                    head = fmaf(d, d, head);
                }
#pragma unroll
                for (int r = S; r <= P - 1; r++) {
                    float d = a[r] - SH[r][cb];
                    mid = fmaf(d, d, mid);
                }
#pragma unroll
                for (int r = P; r < BROWS; r++) {
                    float d = a[r] - SH[r][cb];
                    tail = fmaf(d, d, tail);
                }
                CS[0][oxl][c] = head + mid;   // gh0: rows 0..10
                CS[1][oxl][c] = mid + tail;   // gh0+1: rows 3..13
            }
            __syncthreads();

            // ---- phase 2: horizontal 11-sums + top-16 ----
            if (t < 2 * WREF * 3) {
                int gh = gh0 + ghl;
                if ((unsigned)(3 * gh + oy) <= (unsigned)(H - P)) {
                    for (int oxl = q; oxl < ccnt; oxl += 3) {
                        int oxi = oxbase + oxl;
                        int ox  = oxi - V;
                        int ccand = 3 * gwid + ox;
                        if ((unsigned)ccand > (unsigned)(W - P)) continue;
                        const float* row = &CS[ghl][oxl][3 * gwid];
                        float d = 0.f;
#pragma unroll
                        for (int b = 0; b < P; b++) d += row[b];
                        if (oy == 0 && ox == 0) d = -FLT_MAX;
                        if (d < cmax) {
                            vals[am] = d;
                            unsigned o = (unsigned)((oy + V) * NOFF + oxi);
                            if (am & 1) ip[am >> 1] = (ip[am >> 1] & 0x0000FFFFu) | (o << 16);
                            else        ip[am >> 1] = (ip[am >> 1] & 0xFFFF0000u) | o;
                            cmax = vals[0]; am = 0;
#pragma unroll
                            for (int j = 1; j < KSEL; j++)
                                if (vals[j] > cmax) { cmax = vals[j]; am = j; }
                        }
                    }
                }
            }
            // ---- overlapped: stage next oy's SH during last chunk's phase2 ----
            if (ch == 1 && oy + 1 < s1) {
                for (int i = t; i < BROWS * W; i += 256) {
                    int r = i >> 7, cc = i & 127;
                    int rs = min(max(3 * gh0 + r + oy + 1, 0), H - 1);
                    SH[r][cc] = __ldg(&img[rs * W + cc]);
                }
            }
            __syncthreads();
        }
    }

    // ---- in-CTA merge over q: 3x16 -> 16 per (ghl,gwid); overlay CS ----
    float* MV = &CS[0][0][0];                 // [80 groups][3][16]
    int*   MI = (int*)MV + 80 * 3 * KSEL;
    if (t < 240) {
        int grp = ghl * WREF + gwid;
#pragma unroll
        for (int j = 0; j < KSEL; j++) {
            unsigned o = (j & 1) ? (ip[j >> 1] >> 16) : (ip[j >> 1] & 0xFFFFu);
            MV[(grp * 3 + q) * KSEL + j] = vals[j];
            MI[(grp * 3 + q) * KSEL + j] = (int)o;
        }
    }
    __syncthreads();
    if (t < 80) {
        float* mv = &MV[t * 3 * KSEL];
        int*   mi = &MI[t * 3 * KSEL];
        int gh = gh0 + (t / WREF);
        int gw = t % WREF;
        size_t base = ((((size_t)n * HREF + gh) * NSLC + s) * WREF + gw) * KSEL;
        for (int sel = 0; sel < KSEL; sel++) {
            float bv = FLT_MAX; int bs = 0;
#pragma unroll
            for (int m = 0; m < 3 * KSEL; m++) {
                float v = mv[m];
                if (v < bv) { bv = v; bs = m; }
            }
            g_pv[base + sel] = bv;          // ascending order per slice
            g_pi[base + sel] = mi[bs];
            mv[bs] = FLT_MAX;
        }
    }
}

// ---------------- gather + denoise + scatter (fused slice-merge) ----------
__global__ __launch_bounds__(128) void denoise_kernel(const float* __restrict__ y) {
    __shared__ float Ys[KSEL][YSW];          // stride 130 (bank-spread rows)
    __shared__ float Qp[2][64][5];           // Q e-half partials (padded)
    __shared__ float Qs[KSEL][KSEL + 1];
    __shared__ float Qi[KSEL][KSEL + 1];
    __shared__ float Th[KSEL][KSEL + 1];
    __shared__ float wgt[KSEL];
    __shared__ float q1[KSEL];
    __shared__ float q2s;
    __shared__ int   pr[KSEL], pc[KSEL];
    __shared__ float MS[NSLC * KSEL];
    __shared__ int   MSI[NSLC * KSEL];

    const int g = blockIdx.x;
    const int n = g / LGRP;
    const int rem = g % LGRP;
    const int gh = rem / WREF;
    const int gw = rem % WREF;
    const int tid = threadIdx.x;
    const float* img = y + n * NPIX;

    // stage the 8 sorted slice-lists
    if (tid < NSLC * KSEL) {
        int sl = tid >> 4, m = tid & 15;
        size_t base = (((size_t)(n * HREF + gh) * NSLC + sl) * WREF + gw) * KSEL + m;
        MS[tid]  = g_pv[base];
        MSI[tid] = g_pi[base];
    }
    __syncthreads();

    // thread 0: 8-way sorted merge -> 16 smallest (explicit regs, no local mem)
    if (tid == 0) {
#define HEAD(k) float h##k = MS[k * KSEL]; int hi##k = MSI[k * KSEL]; int p##k = 0;
        HEAD(0) HEAD(1) HEAD(2) HEAD(3) HEAD(4) HEAD(5) HEAD(6) HEAD(7)
#undef HEAD
        for (int sel = 0; sel < KSEL; sel++) {
            float bv = h0; int bsl = 0;
            if (h1 < bv) { bv = h1; bsl = 1; }
            if (h2 < bv) { bv = h2; bsl = 2; }
            if (h3 < bv) { bv = h3; bsl = 3; }
            if (h4 < bv) { bv = h4; bsl = 4; }
            if (h5 < bv) { bv = h5; bsl = 5; }
            if (h6 < bv) { bv = h6; bsl = 6; }
            if (h7 < bv) { bv = h7; bsl = 7; }
            int o;
#define ADV(k) case k: o = hi##k; p##k++; \
    h##k = (p##k < KSEL) ? MS[k * KSEL + p##k] : FLT_MAX; \
    hi##k = (p##k < KSEL) ? MSI[k * KSEL + p##k] : 0; break;
            switch (bsl) { ADV(0) ADV(1) ADV(2) ADV(3) ADV(4) ADV(5) ADV(6) ADV(7) }
#undef ADV
            pr[sel] = 3 * gh + o / NOFF - V;
            pc[sel] = 3 * gw + o % NOFF - V;
        }
    }
    __syncthreads();

    for (int t = tid; t < KSEL * NPATCH; t += 128) {
        int i = t / NPATCH, e = t % NPATCH;
        int a = e / P, b = e % P;
        Ys[i][e] = img[(pr[i] + a) * W + pc[i] + b];
    }
    __syncthreads();

    // Q = Y Y^T + E I : 2x2 register tiling, e split in halves
    {
        int quad = tid & 63;
        int eh   = tid >> 6;
        int i0 = (quad >> 3) << 1, j0 = (quad & 7) << 1;
        float q00 = 0.f, q01 = 0.f, q10 = 0.f, q11 = 0.f;
        int e0 = eh ? 61 : 0, e1 = eh ? NPATCH : 61;
        for (int e = e0; e < e1; e++) {
            float yi0 = Ys[i0][e], yi1 = Ys[i0 + 1][e];
            float yj0 = Ys[j0][e], yj1 = Ys[j0 + 1][e];
            q00 = fmaf(yi0, yj0, q00);
            q01 = fmaf(yi0, yj1, q01);
            q10 = fmaf(yi1, yj0, q10);
            q11 = fmaf(yi1, yj1, q11);
        }
        Qp[eh][quad][0] = q00; Qp[eh][quad][1] = q01;
        Qp[eh][quad][2] = q10; Qp[eh][quad][3] = q11;
    }
    __syncthreads();
    if (tid < 64) {
        int i0 = (tid >> 3) << 1, j0 = (tid & 7) << 1;
        float q00 = Qp[0][tid][0] + Qp[1][tid][0];
        float q01 = Qp[0][tid][1] + Qp[1][tid][1];
        float q10 = Qp[0][tid][2] + Qp[1][tid][2];
        float q11 = Qp[0][tid][3] + Qp[1][tid][3];
        if (i0 == j0) { q00 += E_REG; q11 += E_REG; }
        Qs[i0][j0] = q00;     Qs[i0][j0 + 1] = q01;
        Qs[i0 + 1][j0] = q10; Qs[i0 + 1][j0 + 1] = q11;
    }
    __syncthreads();

    if (tid < 32) {
        int lane = tid;
        for (int j = 0; j < KSEL; j++) {
            if (lane == 0) Qs[j][j] = sqrtf(Qs[j][j]);
            __syncwarp();
            float dj = Qs[j][j];
            if (lane > j && lane < KSEL) Qs[lane][j] /= dj;
            __syncwarp();
            if (lane > j && lane < KSEL) {
                float lij = Qs[lane][j];
                for (int m = j + 1; m <= lane; m++) Qs[lane][m] -= lij * Qs[m][j];
            }
            __syncwarp();
        }
        if (lane < KSEL) {
            float z[KSEL];
            for (int i = 0; i < KSEL; i++) {
                float s = (i == lane) ? 1.f : 0.f;
                for (int j = 0; j < i; j++) s -= Qs[i][j] * z[j];
                z[i] = s / Qs[i][i];
            }
            for (int i = KSEL - 1; i >= 0; i--) {
                float s = z[i];
                for (int j = i + 1; j < KSEL; j++) s -= Qs[j][i] * z[j];
                z[i] = s / Qs[i][i];
            }
            for (int i = 0; i < KSEL; i++) Qi[i][lane] = z[i];
        }
    }
    __syncthreads();

    if (tid < KSEL) {
        float s = 0.f;
        for (int j = 0; j < KSEL; j++) s += Qi[tid][j];
        q1[tid] = s;
    }
    __syncthreads();
    if (tid == 0) {
        float s = 0.f;
        for (int i = 0; i < KSEL; i++) s += q1[i];
        q2s = s;
    }
    __syncthreads();
    for (int t = tid; t < KSEL * KSEL; t += 128) {
        int i = t / KSEL, j = t % KSEL;
        Th[i][j] = ((i == j) ? 1.f : 0.f) - (Qi[i][j] - q1[i] * q1[j] / q2s) * DE_REG;
    }
    __syncthreads();
    if (tid < KSEL) {
        float s = 0.f;
        for (int j = 0; j < KSEL; j++) s += Th[tid][j] * Th[tid][j];
        s = fminf(fmaxf(s, 1.f / (float)KSEL), 1.f);
        wgt[tid] = 1.f / s;
    }
    __syncthreads();

    // X_hat = theta @ Y with theta row in registers; fused float2 scatter
    float2* accI = g_acc + n * NPIX;
    {
        int i  = tid >> 3;       // patch
        int l8 = tid & 7;        // pixel stripe
        float tr[KSEL];
#pragma unroll
        for (int j = 0; j < KSEL; j++) tr[j] = Th[i][j];
        float wv = wgt[i];
        int prI = pr[i], pcI = pc[i];
        for (int e = l8; e < NPATCH; e += 8) {
            float s = 0.f;
#pragma unroll
            for (int j = 0; j < KSEL; j++) s = fmaf(tr[j], Ys[j][e], s);
            int aRow = e / P, b = e % P;
            int pix = (prI + aRow) * W + pcI + b;
            atomicAdd(&accI[pix], make_float2(s * wv, wv));
        }
    }
}

// ---------------- final divide ----------------
__global__ void div_kernel(float* __restrict__ out) {
    int i = blockIdx.x * blockDim.x + threadIdx.x;
    if (i < NIMG * NPIX) {
        float2 v = g_acc[i];
        out[i] = v.x / v.y;
    }
}

extern "C" void kernel_launch(void* const* d_in, const int* in_sizes, int n_in,
                              void* d_out, int out_size) {
    const float* y = (const float*)d_in[0];
    float* out = (float*)d_out;

    bm_kernel<<<NIMG * NBAND * NSLC, 256>>>(y);

    denoise_kernel<<<NIMG * LGRP, 128>>>(y);

    div_kernel<<<(NIMG * NPIX + 255) / 256, 256>>>(out);
}